// round 2
// baseline (speedup 1.0000x reference)
#include <cuda_runtime.h>
#include <math.h>

#define BATCH 512
#define SEQT  100
#define CIN   64
#define G4    40
#define NTOT  (BATCH*SEQT)

// LSTM chunking
#define LCH    100
#define NLCH   (NTOT/LCH)      // 512
#define LWARM  192

// hr-module chunking
#define HCH    100
#define NHCH   (NTOT/HCH)      // 512
#define HWARM  64

// final LIF (over batch) chunking
#define NBCH  8
#define BCH   (BATCH/NBCH)     // 64
#define BWARM 32

#define TAU1f 1.2231301601484298f
#define TAU2f 1.3678794411714423f
#define TAU3f 1.4493289641172216f
#define TAU4f 1.3678794411714423f
#define TH1 0.14f
#define TH2 0.08f
#define TH3 0.06f
#define TH4 0.08f

// ---------------- scratch ----------------
__device__ float  g_xg[NTOT*G4];     // LSTM x-gates + biases
__device__ float  g_cv[NTOT*20];     // conv_out (hr1 input)
__device__ float  g_sk1[NTOT*20];
__device__ float  g_o1[NTOT*20];
__device__ float  g_sk2[NTOT*10];
__device__ float  g_o2[NTOT*10];
__device__ float  g_dp[BATCH*200];
__device__ float  g_fused[BATCH*200];
__device__ double g_red[2];

__device__ __forceinline__ float sigx(float x){ return fmaf(0.5f, tanhf(0.5f*x), 0.5f); }

// ---------------- K0 ----------------
__global__ void k_zero(){ g_red[0]=0.0; g_red[1]=0.0; }

// ---------------- K1: xg[n,g] = sum_c x[b,c,t]*wih[g,c] + bih[g]+bhh[g] ----------------
__global__ void __launch_bounds__(256) k_xgates(const float* __restrict__ x,
                                                const float* __restrict__ wih,
                                                const float* __restrict__ bih,
                                                const float* __restrict__ bhh){
  __shared__ float sx[CIN*SEQT];   // x[b]  (c*100+t)
  __shared__ float sw[CIN*G4];     // sw[c*40+g]
  int b = blockIdx.x, tid = threadIdx.x;
  const float* xb = x + (size_t)b*CIN*SEQT;
  for (int i=tid; i<CIN*SEQT; i+=256) sx[i]=xb[i];
  for (int i=tid; i<CIN*G4; i+=256){ int g=i%G4, c=i/G4; sw[c*G4+g]=wih[g*CIN+c]; }
  __syncthreads();
  for (int idx=tid; idx<SEQT*G4; idx+=256){
    int t = idx / G4, g = idx % G4;
    float acc = bih[g] + bhh[g];
    #pragma unroll 16
    for (int c=0;c<CIN;c++) acc = fmaf(sx[c*SEQT+t], sw[c*G4+g], acc);
    g_xg[((size_t)(b*SEQT+t))*G4 + g] = acc;
  }
}

// ---------------- K2: chunked LSTM scan + fused conv_out ----------------
__global__ void __launch_bounds__(64) k_lstm(const float* __restrict__ whh,
                                             const float* __restrict__ scw,   // sc_w (20,1,10)
                                             const float* __restrict__ scb){
  __shared__ float sh[10];
  __shared__ float sg[40];
  int t = threadIdx.x;
  int n0 = blockIdx.x*LCH, n1 = n0+LCH;
  int s0 = n0 - LWARM; if (s0<0) s0=0;
  int u = t - 40;

  float w[10];
  if (t<40){
    #pragma unroll
    for (int j=0;j<10;j++) w[j]=whh[t*10+j];
  }
  float scr[10]; float scbr=0.f;
  if (u>=0 && u<20){
    #pragma unroll
    for (int j=0;j<10;j++) scr[j]=scw[u*10+j];
    scbr = scb[u];
  }
  float cstate = 0.f;
  if (t<10) sh[t]=0.f;

  float xgv = 0.f;
  if (t<40) xgv = g_xg[(size_t)s0*G4 + t];

  for (int n=s0; n<n1; ++n){
    __syncthreads();                       // sh (h_{n-1}) ready, sg free
    if (t<40){
      float gacc = xgv;
      #pragma unroll
      for (int j=0;j<10;j++) gacc = fmaf(sh[j], w[j], gacc);
      sg[t] = gacc;
      if (n+1<n1) xgv = g_xg[(size_t)(n+1)*G4 + t];
    }
    if (u>=0 && u<20 && (n-1)>=n0){        // conv_out for previous row
      float cvv = scbr;
      #pragma unroll
      for (int j=0;j<10;j++) cvv = fmaf(sh[j], scr[j], cvv);
      g_cv[(size_t)(n-1)*20 + u] = cvv;
    }
    __syncthreads();                       // sg ready, sh free
    if (u>=0 && u<10){
      float gi=sg[u], gf=sg[u+10], gg=sg[u+20], go=sg[u+30];
      cstate = sigx(gf)*cstate + sigx(gi)*tanhf(gg);
      float h = sigx(go)*tanhf(cstate);
      sh[u] = h;
    }
  }
  __syncthreads();
  if (u>=0 && u<20){
    float cvv = scbr;
    #pragma unroll
    for (int j=0;j<10;j++) cvv = fmaf(sh[j], scr[j], cvv);
    g_cv[(size_t)(n1-1)*20 + u] = cvv;
  }
}

// ---------------- K3: skip precompute (fully parallel) ----------------
template<int OD>
__global__ void __launch_bounds__(256) k_skip(const float* __restrict__ in,
                                              const float* __restrict__ W,   // (OD,20)
                                              const float* __restrict__ bb,
                                              float* __restrict__ outp){
  int idx = blockIdx.x*256 + threadIdx.x;
  if (idx >= NTOT*OD) return;
  int n = idx / OD, o = idx % OD;
  float acc = __ldg(&bb[o]);
  const float* row = in + (size_t)n*20;
  #pragma unroll
  for (int f=0; f<20; f++) acc = fmaf(row[f], __ldg(&W[o*20+f]), acc);
  outp[idx] = acc;
}

// ---------------- K4/K5: chunked hr-module scan (one warp / chunk) ----------------
template<int OD>
__global__ void __launch_bounds__(32) k_hr(const float* __restrict__ in,
                                           const float* __restrict__ skip,
                                           const float* __restrict__ conv_w,  // (20,20,3)
                                           const float* __restrict__ conv_b,
                                           const float* __restrict__ fc_w,    // (OD,20)
                                           const float* __restrict__ fc_b,
                                           float* __restrict__ outp){
  __shared__ float sconv[60*32];   // [(f*3+k)*32 + o]
  __shared__ float sfc[20*32];     // [q*32 + o]
  int lane = threadIdx.x;
  int n0 = blockIdx.x*HCH, n1 = n0+HCH;
  int s0 = n0 - HWARM; if (s0<0) s0=0;

  for (int i=lane; i<1200; i+=32){ int o=i/60, r=i%60; sconv[r*32+o]=conv_w[i]; }
  for (int i=lane; i<20*OD; i+=32){ int o=i/20, q=i%20; sfc[q*32+o]=fc_w[i]; }
  float cb = (lane<20) ? conv_b[lane] : 0.f;
  float fb = (lane<OD) ? fc_b[lane]   : 0.f;
  __syncwarp();

  float v1=0.f, v2=0.f, v3=0.f, v4=0.f;
  float xnext = (lane<20) ? in[(size_t)s0*20+lane] : 0.f;
  float snext = (lane<OD) ? skip[(size_t)s0*OD+lane] : 0.f;

  for (int n=s0; n<n1; ++n){
    float xv = xnext, skv = snext;
    if (n+1<n1){
      if (lane<20) xnext = in[(size_t)(n+1)*20+lane];
      if (lane<OD) snext = skip[(size_t)(n+1)*OD+lane];
    }
    v1 = v1 + (xv - v1)/TAU1f;  bool b1 = (v1 - TH1) >= 0.f;  if (b1) v1 = 0.f;
    v2 = v2 + (xv - v2)/TAU2f;  bool b2 = (v2 - TH2) >= 0.f;  if (b2) v2 = 0.f;
    v3 = v3 + (xv - v3)/TAU3f;  bool b3 = (v3 - TH3) >= 0.f;  if (b3) v3 = 0.f;
    unsigned m1 = __ballot_sync(0xffffffffu, b1);
    unsigned m2 = __ballot_sync(0xffffffffu, b2);
    unsigned m3 = __ballot_sync(0xffffffffu, b3);
    float acc = cb;
    unsigned mm = m1;
    while (mm){ int f=__ffs(mm)-1; mm &= mm-1; acc += sconv[(f*3+0)*32+lane]; }
    mm = m2;
    while (mm){ int f=__ffs(mm)-1; mm &= mm-1; acc += sconv[(f*3+1)*32+lane]; }
    mm = m3;
    while (mm){ int f=__ffs(mm)-1; mm &= mm-1; acc += sconv[(f*3+2)*32+lane]; }
    v4 = v4 + (acc - v4)/TAU4f;  bool b4 = (lane<20) && ((v4 - TH4) >= 0.f);  if (b4) v4 = 0.f;
    unsigned m4 = __ballot_sync(0xffffffffu, b4);
    if (n >= n0 && lane < OD){
      float out = fb + skv;
      mm = m4;
      while (mm){ int q=__ffs(mm)-1; mm &= mm-1; out += sfc[q*32+lane]; }
      outp[(size_t)n*OD + lane] = out;
    }
  }
}

// ---------------- K6: final LIF over batch + differential pairs ----------------
__global__ void __launch_bounds__(200) k_flif(){
  int tid = threadIdx.x;          // 200 = (d,j)
  int d = tid / 20, j = tid % 20;
  int b0 = blockIdx.x*BCH, b1e = b0+BCH;
  int s0 = b0 - BWARM; if (s0<0) s0=0;
  float v[5] = {0.f,0.f,0.f,0.f,0.f};
  for (int b=s0; b<b1e; ++b){
    float sp[5];
    #pragma unroll
    for (int r=0;r<5;r++){
      float xv = g_o2[((size_t)b*SEQT + 5*j + r)*10 + d];
      v[r] = v[r] + (xv - v[r])/TAU4f;
      bool s = (v[r] - TH4) >= 0.f;
      if (s) v[r] = 0.f;
      sp[r] = s ? 1.f : 0.f;
    }
    if (b >= b0){
      float dp = (sp[3] + sp[4] - sp[0] - sp[1]) * 0.5f;
      g_dp[(size_t)b*200 + d*20 + j] = dp;
    }
  }
}

// ---------------- K7: fused = dp*avg, global moments ----------------
__global__ void __launch_bounds__(256) k_fused(){
  __shared__ float sdp[200];
  __shared__ float savg[20];
  __shared__ float rs[256];
  __shared__ float rq[256];
  int b = blockIdx.x, tid = threadIdx.x;
  if (tid<200) sdp[tid] = g_dp[(size_t)b*200 + tid];
  __syncthreads();
  if (tid<20){
    float a=0.f;
    #pragma unroll
    for (int d=0;d<10;d++) a += sdp[d*20+tid];
    savg[tid] = a*0.1f;
  }
  __syncthreads();
  float fu = 0.f;
  if (tid<200){
    fu = sdp[tid]*savg[tid%20];
    g_fused[(size_t)b*200 + tid] = fu;
  }
  rs[tid]=fu; rq[tid]=fu*fu;
  __syncthreads();
  for (int s=128; s>0; s>>=1){
    if (tid<s){ rs[tid]+=rs[tid+s]; rq[tid]+=rq[tid+s]; }
    __syncthreads();
  }
  if (tid==0){
    atomicAdd(&g_red[0], (double)rs[0]);
    atomicAdd(&g_red[1], (double)rq[0]);
  }
}

// ---------------- K8: BN + logits + log_softmax ----------------
__global__ void __launch_bounds__(32) k_out(const float* __restrict__ gamma,
                                            const float* __restrict__ beta,
                                            const float* __restrict__ clsw,  // (3,200)
                                            const float* __restrict__ clsb,
                                            float* __restrict__ out){
  int b = blockIdx.x, lane = threadIdx.x;
  double inv = 1.0/(double)(BATCH*200);
  double mean = g_red[0]*inv;
  double var  = g_red[1]*inv - mean*mean;
  float fm = (float)mean;
  float rstd = (float)(1.0/sqrt(var + 1e-5));
  float gm = __ldg(&gamma[0]), bt = __ldg(&beta[0]);
  float p0=0.f, p1=0.f, p2=0.f;
  for (int j=lane; j<200; j+=32){
    float bnv = fmaf((g_fused[(size_t)b*200+j]-fm)*rstd, gm, bt);
    p0 = fmaf(bnv, __ldg(&clsw[j]),     p0);
    p1 = fmaf(bnv, __ldg(&clsw[200+j]), p1);
    p2 = fmaf(bnv, __ldg(&clsw[400+j]), p2);
  }
  #pragma unroll
  for (int s=16;s>0;s>>=1){
    p0 += __shfl_down_sync(0xffffffffu, p0, s);
    p1 += __shfl_down_sync(0xffffffffu, p1, s);
    p2 += __shfl_down_sync(0xffffffffu, p2, s);
  }
  if (lane==0){
    float l0 = p0 + __ldg(&clsb[0]);
    float l1 = p1 + __ldg(&clsb[1]);
    float l2 = p2 + __ldg(&clsb[2]);
    float m = fmaxf(l0, fmaxf(l1,l2));
    float lse = m + logf(expf(l0-m)+expf(l1-m)+expf(l2-m));
    out[b*3+0] = l0 - lse;
    out[b*3+1] = l1 - lse;
    out[b*3+2] = l2 - lse;
  }
}

// ---------------- launch ----------------
extern "C" void kernel_launch(void* const* d_in, const int* in_sizes, int n_in,
                              void* d_out, int out_size){
  (void)in_sizes; (void)n_in; (void)out_size;
  const float* x        = (const float*)d_in[0];
  const float* wih      = (const float*)d_in[1];
  const float* whh      = (const float*)d_in[2];
  const float* bih      = (const float*)d_in[3];
  const float* bhh      = (const float*)d_in[4];
  const float* sc_w     = (const float*)d_in[5];
  const float* sc_b     = (const float*)d_in[6];
  const float* c1w      = (const float*)d_in[7];
  const float* c1b      = (const float*)d_in[8];
  const float* f1w      = (const float*)d_in[9];
  const float* f1b      = (const float*)d_in[10];
  const float* s1w      = (const float*)d_in[11];
  const float* s1b      = (const float*)d_in[12];
  const float* c2w      = (const float*)d_in[13];
  const float* c2b      = (const float*)d_in[14];
  const float* f2w      = (const float*)d_in[15];
  const float* f2b      = (const float*)d_in[16];
  const float* s2w      = (const float*)d_in[17];
  const float* s2b      = (const float*)d_in[18];
  const float* gamma    = (const float*)d_in[19];
  const float* beta     = (const float*)d_in[20];
  const float* clsw     = (const float*)d_in[21];
  const float* clsb     = (const float*)d_in[22];
  float* out = (float*)d_out;

  float *p_cv, *p_sk1, *p_o1, *p_sk2, *p_o2;
  cudaGetSymbolAddress((void**)&p_cv,  g_cv);
  cudaGetSymbolAddress((void**)&p_sk1, g_sk1);
  cudaGetSymbolAddress((void**)&p_o1,  g_o1);
  cudaGetSymbolAddress((void**)&p_sk2, g_sk2);
  cudaGetSymbolAddress((void**)&p_o2,  g_o2);

  k_zero<<<1,1>>>();
  k_xgates<<<BATCH,256>>>(x, wih, bih, bhh);
  k_lstm<<<NLCH,64>>>(whh, sc_w, sc_b);
  k_skip<20><<<(NTOT*20+255)/256,256>>>(p_cv, s1w, s1b, p_sk1);
  k_hr<20><<<NHCH,32>>>(p_cv, p_sk1, c1w, c1b, f1w, f1b, p_o1);
  k_skip<10><<<(NTOT*10+255)/256,256>>>(p_o1, s2w, s2b, p_sk2);
  k_hr<10><<<NHCH,32>>>(p_o1, p_sk2, c2w, c2b, f2w, f2b, p_o2);
  k_flif<<<NBCH,200>>>();
  k_fused<<<BATCH,256>>>();
  k_out<<<BATCH,32>>>(gamma, beta, clsw, clsb, out);
}

// round 3
// speedup vs baseline: 2.9685x; 2.9685x over previous
#include <cuda_runtime.h>
#include <math.h>

#define BATCH 512
#define SEQT  100
#define CIN   64
#define G4    40
#define NTOT  (BATCH*SEQT)

// LSTM chunking
#define LCH    50
#define NLCH   (NTOT/LCH)      // 1024
#define LWARM  128

// hr-module chunking
#define HCH    50
#define NHCH   (NTOT/HCH)      // 1024
#define HWARM  64

// final LIF (over batch) chunking
#define NBCH  64
#define BCH   (BATCH/NBCH)     // 8
#define BWARM 32

#define TAU1f 1.2231301601484298f
#define TAU2f 1.3678794411714423f
#define TAU3f 1.4493289641172216f
#define TAU4f 1.3678794411714423f
#define TH1 0.14f
#define TH2 0.08f
#define TH3 0.06f
#define TH4 0.08f

// ---------------- scratch ----------------
__device__ float  g_xg[NTOT*G4];     // LSTM x-gates + biases
__device__ float  g_cv[NTOT*20];     // conv_out (hr1 input)
__device__ float  g_sk1[NTOT*20];
__device__ float  g_o1[NTOT*20];
__device__ float  g_sk2[NTOT*10];
__device__ float  g_o2[NTOT*10];
__device__ unsigned g_mA[NTOT];      // spike mask bits 0..31   (units f*3+k)
__device__ unsigned g_mB[NTOT];      // spike mask bits 32..59
__device__ float  g_dp[BATCH*200];
__device__ float  g_fused[BATCH*200];
__device__ double g_red[2];

__device__ __forceinline__ float sigx(float x){ return fmaf(0.5f, tanhf(0.5f*x), 0.5f); }

// ---------------- K0 ----------------
__global__ void k_zero(){ g_red[0]=0.0; g_red[1]=0.0; }

// ---------------- K1: xg[n,g] = sum_c x[b,c,t]*wih[g,c] + bih[g]+bhh[g] ----------------
// 4t x 4g register tile per thread: 250 active threads (25 t-quads x 10 g-quads)
__global__ void __launch_bounds__(256) k_xgates(const float* __restrict__ x,
                                                const float* __restrict__ wih,
                                                const float* __restrict__ bih,
                                                const float* __restrict__ bhh){
  __shared__ float sx[CIN*SEQT];   // [c*100+t]
  __shared__ float sw[CIN*G4];     // [c*40+g]
  int b = blockIdx.x, tid = threadIdx.x;
  const float* xb = x + (size_t)b*CIN*SEQT;
  for (int i=tid; i<CIN*SEQT; i+=256) sx[i]=xb[i];
  for (int i=tid; i<CIN*G4; i+=256){ int g=i%G4, c=i/G4; sw[c*G4+g]=wih[g*CIN+c]; }
  __syncthreads();
  if (tid < 250){
    int tq = tid/10, gq = tid%10;
    int tb = tq*4, gb = gq*4;
    float bz[4];
    #pragma unroll
    for (int gi=0; gi<4; gi++) bz[gi] = bih[gb+gi] + bhh[gb+gi];
    float a[4][4];
    #pragma unroll
    for (int ti=0; ti<4; ti++)
      #pragma unroll
      for (int gi=0; gi<4; gi++) a[ti][gi] = bz[gi];
    #pragma unroll 8
    for (int c=0; c<CIN; c++){
      float4 wv = *(const float4*)&sw[c*G4+gb];
      float xr[4];
      #pragma unroll
      for (int ti=0; ti<4; ti++) xr[ti] = sx[c*SEQT+tb+ti];
      #pragma unroll
      for (int ti=0; ti<4; ti++){
        a[ti][0]=fmaf(xr[ti],wv.x,a[ti][0]);
        a[ti][1]=fmaf(xr[ti],wv.y,a[ti][1]);
        a[ti][2]=fmaf(xr[ti],wv.z,a[ti][2]);
        a[ti][3]=fmaf(xr[ti],wv.w,a[ti][3]);
      }
    }
    #pragma unroll
    for (int ti=0; ti<4; ti++){
      float4 o = make_float4(a[ti][0],a[ti][1],a[ti][2],a[ti][3]);
      *(float4*)&g_xg[((size_t)(b*SEQT+tb+ti))*G4 + gb] = o;
    }
  }
}

// ---------------- K2: chunked LSTM scan + fused conv_out ----------------
__global__ void __launch_bounds__(64) k_lstm(const float* __restrict__ whh,
                                             const float* __restrict__ scw,   // (20,1,10)
                                             const float* __restrict__ scb){
  __shared__ float sh[10];
  __shared__ float sg[40];     // ACTIVATED gate values
  int t = threadIdx.x;
  int n0 = blockIdx.x*LCH, n1 = n0+LCH;
  int s0 = n0 - LWARM; if (s0<0) s0=0;
  int u = t - 40;

  float w[10];
  if (t<40){
    #pragma unroll
    for (int j=0;j<10;j++) w[j]=whh[t*10+j];
  }
  // nonlinearity params: sigmoid = 0.5*tanh(0.5x)+0.5 ; g-gate = tanh
  bool isg = (t>=20 && t<30);
  float S = isg ? 1.0f : 0.5f;
  float Cc = isg ? 0.0f : 0.5f;

  float scr[10]; float scbr=0.f;
  if (u>=0 && u<20){
    #pragma unroll
    for (int j=0;j<10;j++) scr[j]=scw[u*10+j];
    scbr = scb[u];
  }
  float cstate = 0.f;
  if (t<10) sh[t]=0.f;

  float xgv = 0.f;
  if (t<40) xgv = g_xg[(size_t)s0*G4 + t];

  for (int n=s0; n<n1; ++n){
    __syncthreads();                       // sh (h_{n-1}) ready
    if (t<40){
      float gacc = xgv;
      float g0=0.f, g1=0.f;
      #pragma unroll
      for (int j=0;j<10;j+=2){ g0=fmaf(sh[j],w[j],g0); g1=fmaf(sh[j+1],w[j+1],g1); }
      gacc += g0+g1;
      sg[t] = fmaf(S, tanhf(S*gacc), Cc);  // activated gate
      if (n+1<n1) xgv = g_xg[(size_t)(n+1)*G4 + t];
    }
    if (u>=0 && u<20 && (n-1)>=n0){        // conv_out for previous row
      float cvv = scbr;
      #pragma unroll
      for (int j=0;j<10;j++) cvv = fmaf(sh[j], scr[j], cvv);
      g_cv[(size_t)(n-1)*20 + u] = cvv;
    }
    __syncthreads();                       // sg ready
    if (u>=0 && u<10){
      cstate = sg[u+10]*cstate + sg[u]*sg[u+20];
      sh[u] = sg[u+30]*tanhf(cstate);
    }
  }
  __syncthreads();
  if (u>=0 && u<20){
    float cvv = scbr;
    #pragma unroll
    for (int j=0;j<10;j++) cvv = fmaf(sh[j], scr[j], cvv);
    g_cv[(size_t)(n1-1)*20 + u] = cvv;
  }
}

// ---------------- K3: skip precompute, one thread per row ----------------
template<int OD>
__global__ void __launch_bounds__(256) k_skip(const float* __restrict__ in,
                                              const float* __restrict__ W,   // (OD,20)
                                              const float* __restrict__ bb,
                                              float* __restrict__ outp){
  __shared__ float sw[OD*20];
  __shared__ float sb[OD];
  int tid = threadIdx.x;
  for (int i=tid; i<OD*20; i+=256) sw[i]=W[i];
  if (tid<OD) sb[tid]=bb[tid];
  __syncthreads();
  int n = blockIdx.x*256 + tid;
  if (n >= NTOT) return;
  float r[20];
  const float4* rp = (const float4*)(in + (size_t)n*20);
  #pragma unroll
  for (int q=0;q<5;q++){ float4 v=rp[q]; r[4*q]=v.x; r[4*q+1]=v.y; r[4*q+2]=v.z; r[4*q+3]=v.w; }
  float o[OD];
  #pragma unroll
  for (int j=0;j<OD;j++) o[j]=sb[j];
  #pragma unroll
  for (int f=0;f<20;f++){
    float xv = r[f];
    #pragma unroll
    for (int j=0;j<OD;j++) o[j]=fmaf(xv, sw[j*20+f], o[j]);
  }
  #pragma unroll
  for (int j=0;j<OD;j++) outp[(size_t)n*OD+j]=o[j];
}

// ---------------- K4a: LIF1-3 spike mask generation (parallel over features) ----------------
__global__ void __launch_bounds__(64) k_mask(const float* __restrict__ in){
  int tid = threadIdx.x;           // unit = f*3+k, tid<60 active
  int n0 = blockIdx.x*HCH, n1 = n0+HCH;
  int s0 = n0 - HWARM; if (s0<0) s0=0;
  int f = tid/3, k = tid%3;
  bool act = tid < 60;
  float tau = (k==0)?TAU1f:((k==1)?TAU2f:TAU3f);
  float th  = (k==0)?TH1 :((k==1)?TH2 :TH3);
  float v = 0.f;
  int warp = tid>>5;
  float xnext = act ? in[(size_t)s0*20+f] : 0.f;
  for (int n=s0; n<n1; ++n){
    float xv = xnext;
    if (n+1<n1 && act) xnext = in[(size_t)(n+1)*20+f];
    v = v + (xv - v)/tau;
    bool s = act && ((v - th) >= 0.f);
    if (s) v = 0.f;
    unsigned m = __ballot_sync(0xffffffffu, s);
    if ((tid&31)==0 && n>=n0){
      if (warp==0) g_mA[n]=m; else g_mB[n]=m;
    }
  }
}

// ---------------- K4b: LIF4 + conv(spikes) + fc + skip (serial, one warp/chunk) ----------------
template<int OD>
__global__ void __launch_bounds__(32) k_hrb(const float* __restrict__ skip,
                                            const float* __restrict__ conv_w,  // (20,20,3)
                                            const float* __restrict__ conv_b,
                                            const float* __restrict__ fc_w,    // (OD,20)
                                            const float* __restrict__ fc_b,
                                            float* __restrict__ outp){
  int lane = threadIdx.x;
  int n0 = blockIdx.x*HCH, n1 = n0+HCH;
  int s0 = n0 - HWARM; if (s0<0) s0=0;

  int lo = (lane<20)?lane:19;
  float wr[60];
  #pragma unroll
  for (int i=0;i<60;i++) wr[i] = conv_w[lo*60+i];      // w[o][f*3+k]
  int lf = (lane<OD)?lane:(OD-1);
  float fr[20];
  #pragma unroll
  for (int q=0;q<20;q++) fr[q] = fc_w[lf*20+q];
  float cb = (lane<20) ? conv_b[lane] : 0.f;
  float fb = (lane<OD) ? fc_b[lane]   : 0.f;

  float v4 = 0.f;
  unsigned mAv = g_mA[s0], mBv = g_mB[s0];
  float skv = (lane<OD) ? skip[(size_t)s0*OD+lane] : 0.f;

  for (int n=s0; n<n1; ++n){
    unsigned ma = mAv, mb = mBv; float sk = skv;
    if (n+1<n1){
      mAv = g_mA[n+1]; mBv = g_mB[n+1];
      if (lane<OD) skv = skip[(size_t)(n+1)*OD+lane];
    }
    float a0=cb, a1=0.f, a2=0.f, a3=0.f;
    #pragma unroll
    for (int i=0;i<32;i+=4){
      if (ma & (1u<<(i  ))) a0 += wr[i  ];
      if (ma & (1u<<(i+1))) a1 += wr[i+1];
      if (ma & (1u<<(i+2))) a2 += wr[i+2];
      if (ma & (1u<<(i+3))) a3 += wr[i+3];
    }
    #pragma unroll
    for (int i=0;i<28;i+=4){
      if (mb & (1u<<(i  ))) a0 += wr[32+i  ];
      if (mb & (1u<<(i+1))) a1 += wr[32+i+1];
      if (mb & (1u<<(i+2))) a2 += wr[32+i+2];
      if (mb & (1u<<(i+3))) a3 += wr[32+i+3];
    }
    float acc = (a0+a1)+(a2+a3);
    v4 = v4 + (acc - v4)/TAU4f;
    bool b4 = (lane<20) && ((v4 - TH4) >= 0.f);
    if (b4) v4 = 0.f;
    unsigned m4 = __ballot_sync(0xffffffffu, b4);
    if (n >= n0 && lane < OD){
      float o0 = fb + sk, o1 = 0.f;
      #pragma unroll
      for (int q=0;q<20;q+=2){
        if (m4 & (1u<<q))     o0 += fr[q];
        if (m4 & (1u<<(q+1))) o1 += fr[q+1];
      }
      outp[(size_t)n*OD + lane] = o0+o1;
    }
  }
}

// ---------------- K6: final LIF over batch + differential pairs ----------------
__global__ void __launch_bounds__(200) k_flif(){
  int tid = threadIdx.x;
  int d = tid % 10, j = tid / 10;     // d contiguous -> coalesced-ish
  int b0 = blockIdx.x*BCH, b1e = b0+BCH;
  int s0 = b0 - BWARM; if (s0<0) s0=0;
  float v[5] = {0.f,0.f,0.f,0.f,0.f};
  for (int b=s0; b<b1e; ++b){
    float sp[5];
    #pragma unroll
    for (int r=0;r<5;r++){
      float xv = g_o2[((size_t)b*SEQT + 5*j + r)*10 + d];
      v[r] = v[r] + (xv - v[r])/TAU4f;
      bool s = (v[r] - TH4) >= 0.f;
      if (s) v[r] = 0.f;
      sp[r] = s ? 1.f : 0.f;
    }
    if (b >= b0){
      float dp = (sp[3] + sp[4] - sp[0] - sp[1]) * 0.5f;
      g_dp[(size_t)b*200 + d*20 + j] = dp;
    }
  }
}

// ---------------- K7: fused = dp*avg, global moments ----------------
__global__ void __launch_bounds__(256) k_fused(){
  __shared__ float sdp[200];
  __shared__ float savg[20];
  __shared__ float rs[256];
  __shared__ float rq[256];
  int b = blockIdx.x, tid = threadIdx.x;
  if (tid<200) sdp[tid] = g_dp[(size_t)b*200 + tid];
  __syncthreads();
  if (tid<20){
    float a=0.f;
    #pragma unroll
    for (int d=0;d<10;d++) a += sdp[d*20+tid];
    savg[tid] = a*0.1f;
  }
  __syncthreads();
  float fu = 0.f;
  if (tid<200){
    fu = sdp[tid]*savg[tid%20];
    g_fused[(size_t)b*200 + tid] = fu;
  }
  rs[tid]=fu; rq[tid]=fu*fu;
  __syncthreads();
  for (int s=128; s>0; s>>=1){
    if (tid<s){ rs[tid]+=rs[tid+s]; rq[tid]+=rq[tid+s]; }
    __syncthreads();
  }
  if (tid==0){
    atomicAdd(&g_red[0], (double)rs[0]);
    atomicAdd(&g_red[1], (double)rq[0]);
  }
}

// ---------------- K8: BN + logits + log_softmax ----------------
__global__ void __launch_bounds__(32) k_out(const float* __restrict__ gamma,
                                            const float* __restrict__ beta,
                                            const float* __restrict__ clsw,
                                            const float* __restrict__ clsb,
                                            float* __restrict__ out){
  int b = blockIdx.x, lane = threadIdx.x;
  double inv = 1.0/(double)(BATCH*200);
  double mean = g_red[0]*inv;
  double var  = g_red[1]*inv - mean*mean;
  float fm = (float)mean;
  float rstd = (float)(1.0/sqrt(var + 1e-5));
  float gm = __ldg(&gamma[0]), bt = __ldg(&beta[0]);
  float p0=0.f, p1=0.f, p2=0.f;
  for (int j=lane; j<200; j+=32){
    float bnv = fmaf((g_fused[(size_t)b*200+j]-fm)*rstd, gm, bt);
    p0 = fmaf(bnv, __ldg(&clsw[j]),     p0);
    p1 = fmaf(bnv, __ldg(&clsw[200+j]), p1);
    p2 = fmaf(bnv, __ldg(&clsw[400+j]), p2);
  }
  #pragma unroll
  for (int s=16;s>0;s>>=1){
    p0 += __shfl_down_sync(0xffffffffu, p0, s);
    p1 += __shfl_down_sync(0xffffffffu, p1, s);
    p2 += __shfl_down_sync(0xffffffffu, p2, s);
  }
  if (lane==0){
    float l0 = p0 + __ldg(&clsb[0]);
    float l1 = p1 + __ldg(&clsb[1]);
    float l2 = p2 + __ldg(&clsb[2]);
    float m = fmaxf(l0, fmaxf(l1,l2));
    float lse = m + logf(expf(l0-m)+expf(l1-m)+expf(l2-m));
    out[b*3+0] = l0 - lse;
    out[b*3+1] = l1 - lse;
    out[b*3+2] = l2 - lse;
  }
}

// ---------------- launch ----------------
extern "C" void kernel_launch(void* const* d_in, const int* in_sizes, int n_in,
                              void* d_out, int out_size){
  (void)in_sizes; (void)n_in; (void)out_size;
  const float* x        = (const float*)d_in[0];
  const float* wih      = (const float*)d_in[1];
  const float* whh      = (const float*)d_in[2];
  const float* bih      = (const float*)d_in[3];
  const float* bhh      = (const float*)d_in[4];
  const float* sc_w     = (const float*)d_in[5];
  const float* sc_b     = (const float*)d_in[6];
  const float* c1w      = (const float*)d_in[7];
  const float* c1b      = (const float*)d_in[8];
  const float* f1w      = (const float*)d_in[9];
  const float* f1b      = (const float*)d_in[10];
  const float* s1w      = (const float*)d_in[11];
  const float* s1b      = (const float*)d_in[12];
  const float* c2w      = (const float*)d_in[13];
  const float* c2b      = (const float*)d_in[14];
  const float* f2w      = (const float*)d_in[15];
  const float* f2b      = (const float*)d_in[16];
  const float* s2w      = (const float*)d_in[17];
  const float* s2b      = (const float*)d_in[18];
  const float* gamma    = (const float*)d_in[19];
  const float* beta     = (const float*)d_in[20];
  const float* clsw     = (const float*)d_in[21];
  const float* clsb     = (const float*)d_in[22];
  float* out = (float*)d_out;

  float *p_cv, *p_sk1, *p_o1, *p_sk2, *p_o2;
  cudaGetSymbolAddress((void**)&p_cv,  g_cv);
  cudaGetSymbolAddress((void**)&p_sk1, g_sk1);
  cudaGetSymbolAddress((void**)&p_o1,  g_o1);
  cudaGetSymbolAddress((void**)&p_sk2, g_sk2);
  cudaGetSymbolAddress((void**)&p_o2,  g_o2);

  k_zero<<<1,1>>>();
  k_xgates<<<BATCH,256>>>(x, wih, bih, bhh);
  k_lstm<<<NLCH,64>>>(whh, sc_w, sc_b);
  k_skip<20><<<(NTOT+255)/256,256>>>(p_cv, s1w, s1b, p_sk1);
  k_mask<<<NHCH,64>>>(p_cv);
  k_hrb<20><<<NHCH,32>>>(p_sk1, c1w, c1b, f1w, f1b, p_o1);
  k_skip<10><<<(NTOT+255)/256,256>>>(p_o1, s2w, s2b, p_sk2);
  k_mask<<<NHCH,64>>>(p_o1);
  k_hrb<10><<<NHCH,32>>>(p_sk2, c2w, c2b, f2w, f2b, p_o2);
  k_flif<<<NBCH,200>>>();
  k_fused<<<BATCH,256>>>();
  k_out<<<BATCH,32>>>(gamma, beta, clsw, clsb, out);
}

// round 4
// speedup vs baseline: 3.1976x; 1.0772x over previous
#include <cuda_runtime.h>
#include <math.h>

#define BATCH 512
#define SEQT  100
#define CIN   64
#define G4    40
#define NTOT  (BATCH*SEQT)

// LSTM chunking
#define LCH    50
#define NLCH   (NTOT/LCH)      // 1024
#define LWARM  96

// hr-module chunking
#define HCH    50
#define NHCH   (NTOT/HCH)      // 1024
#define HWARM  32

// final LIF (over batch) chunking
#define NBCH  128
#define BCH   (BATCH/NBCH)     // 4
#define BWARM 32

#define TAU1f 1.2231301601484298f
#define TAU2f 1.3678794411714423f
#define TAU3f 1.4493289641172216f
#define TAU4f 1.3678794411714423f
#define TH1 0.14f
#define TH2 0.08f
#define TH3 0.06f
#define TH4 0.08f

// ---------------- scratch ----------------
__device__ float  g_xg[NTOT*G4];     // LSTM x-gates + biases
__device__ float  g_cv[NTOT*20];     // conv_out (hr1 input)
__device__ float  g_c[NTOT*20];      // spike-conv output (LIF4 input)
__device__ float  g_o1[NTOT*20];
__device__ float  g_o2[NTOT*10];
__device__ unsigned g_mA[NTOT];      // spike mask bits 0..31   (unit f*3+k)
__device__ unsigned g_mB[NTOT];      // spike mask bits 32..59
__device__ unsigned g_m4[NTOT];      // LIF4 spike mask (20 bits)
__device__ float  g_dp[BATCH*200];
__device__ float  g_fused[BATCH*200];
__device__ double g_red[2];

// ---------------- K1: xg[n,g] = sum_c x[b,c,t]*wih[g,c] + bih[g]+bhh[g] ----------------
__global__ void __launch_bounds__(256) k_xgates(const float* __restrict__ x,
                                                const float* __restrict__ wih,
                                                const float* __restrict__ bih,
                                                const float* __restrict__ bhh){
  __shared__ float sx[CIN*SEQT];   // [c*100+t]
  __shared__ float sw[CIN*G4];     // [c*40+g]
  int b = blockIdx.x, tid = threadIdx.x;
  if (b==0 && tid==255){ g_red[0]=0.0; g_red[1]=0.0; }
  const float* xb = x + (size_t)b*CIN*SEQT;
  for (int i=tid; i<CIN*SEQT; i+=256) sx[i]=xb[i];
  for (int i=tid; i<CIN*G4; i+=256){ int g=i%G4, c=i/G4; sw[c*G4+g]=wih[g*CIN+c]; }
  __syncthreads();
  if (tid < 250){
    int tq = tid/10, gq = tid%10;
    int tb = tq*4, gb = gq*4;
    float bz[4];
    #pragma unroll
    for (int gi=0; gi<4; gi++) bz[gi] = bih[gb+gi] + bhh[gb+gi];
    float a[4][4];
    #pragma unroll
    for (int ti=0; ti<4; ti++)
      #pragma unroll
      for (int gi=0; gi<4; gi++) a[ti][gi] = bz[gi];
    #pragma unroll 8
    for (int c=0; c<CIN; c++){
      float4 wv = *(const float4*)&sw[c*G4+gb];
      float xr[4];
      #pragma unroll
      for (int ti=0; ti<4; ti++) xr[ti] = sx[c*SEQT+tb+ti];
      #pragma unroll
      for (int ti=0; ti<4; ti++){
        a[ti][0]=fmaf(xr[ti],wv.x,a[ti][0]);
        a[ti][1]=fmaf(xr[ti],wv.y,a[ti][1]);
        a[ti][2]=fmaf(xr[ti],wv.z,a[ti][2]);
        a[ti][3]=fmaf(xr[ti],wv.w,a[ti][3]);
      }
    }
    #pragma unroll
    for (int ti=0; ti<4; ti++){
      float4 o = make_float4(a[ti][0],a[ti][1],a[ti][2],a[ti][3]);
      *(float4*)&g_xg[((size_t)(b*SEQT+tb+ti))*G4 + gb] = o;
    }
  }
}

// ---------------- K2: chunked LSTM scan, single warp, shuffle exchange ----------------
// lane role: role=lane/10 -> 0:i, 1:f, 2:g, 3:(30,31 spare -> o rows). All lanes also
// compute the o-gate for unit j=lane%10 and maintain replicated (c,h) state for unit j.
__global__ void __launch_bounds__(32) k_lstm(const float* __restrict__ whh,
                                             const float* __restrict__ scw,   // (20,1,10)
                                             const float* __restrict__ scb){
  int lane = threadIdx.x;
  int j = lane % 10;
  int role = lane / 10;
  int gidx = (role<3) ? role*10 + j : 30 + j;
  int n0 = blockIdx.x*LCH, n1 = n0+LCH;
  int s0 = n0 - LWARM; if (s0<0) s0=0;

  float w[10], wo[10];
  #pragma unroll
  for (int k=0;k<10;k++){ w[k]=whh[gidx*10+k]; wo[k]=whh[(30+j)*10+k]; }
  float S = (role==2) ? 1.0f : 0.5f;
  float Cc = (role==2) ? 0.0f : 0.5f;
  int oo = (lane<20)?lane:(lane-20);
  float scr[10];
  #pragma unroll
  for (int k=0;k<10;k++) scr[k]=scw[oo*10+k];
  float scbr = scb[oo];

  float c=0.f, h=0.f;
  float xgv = g_xg[(size_t)s0*G4 + gidx];
  float xgo = g_xg[(size_t)s0*G4 + 30 + j];

  for (int n=s0; n<n1; ++n){
    float a0=0.f, a1=0.f, b0=0.f, b1=0.f, cv=scbr;
    #pragma unroll
    for (int k=0;k<10;k+=2){
      float h0 = __shfl_sync(0xffffffffu, h, k);
      float h1 = __shfl_sync(0xffffffffu, h, k+1);
      a0 = fmaf(h0, w[k],  a0);   a1 = fmaf(h1, w[k+1],  a1);
      b0 = fmaf(h0, wo[k], b0);   b1 = fmaf(h1, wo[k+1], b1);
      cv = fmaf(h0, scr[k], cv);  cv = fmaf(h1, scr[k+1], cv);
    }
    float acc  = xgv + (a0+a1);
    float acco = xgo + (b0+b1);
    if (lane<20 && (n-1)>=n0) g_cv[(size_t)(n-1)*20 + lane] = cv;
    if (n+1<n1){
      xgv = g_xg[(size_t)(n+1)*G4 + gidx];
      xgo = g_xg[(size_t)(n+1)*G4 + 30 + j];
    }
    float act1 = fmaf(S,    tanhf(S*acc),     Cc);
    float act2 = fmaf(0.5f, tanhf(0.5f*acco), 0.5f);
    float si = __shfl_sync(0xffffffffu, act1, j);
    float sf = __shfl_sync(0xffffffffu, act1, 10+j);
    float sg = __shfl_sync(0xffffffffu, act1, 20+j);
    float so = __shfl_sync(0xffffffffu, act2, j);
    c = sf*c + si*sg;
    h = so * tanhf(c);
  }
  float cv = scbr;
  #pragma unroll
  for (int k=0;k<10;k++) cv = fmaf(__shfl_sync(0xffffffffu, h, k), scr[k], cv);
  if (lane<20) g_cv[(size_t)(n1-1)*20 + lane] = cv;
}

// ---------------- K3: LIF1-3 spike mask generation (chunked, cheap) ----------------
__global__ void __launch_bounds__(64) k_mask(const float* __restrict__ in){
  int tid = threadIdx.x;           // unit = f*3+k, tid<60 active
  int n0 = blockIdx.x*HCH, n1 = n0+HCH;
  int s0 = n0 - HWARM; if (s0<0) s0=0;
  int f = tid/3, k = tid%3;
  bool act = tid < 60;
  float tau = (k==0)?TAU1f:((k==1)?TAU2f:TAU3f);
  float th  = (k==0)?TH1 :((k==1)?TH2 :TH3);
  float v = 0.f;
  int warp = tid>>5;
  float xnext = act ? in[(size_t)s0*20+f] : 0.f;
  for (int n=s0; n<n1; ++n){
    float xv = xnext;
    if (n+1<n1 && act) xnext = in[(size_t)(n+1)*20+f];
    v = v + (xv - v)/tau;
    bool s = act && ((v - th) >= 0.f);
    if (s) v = 0.f;
    unsigned m = __ballot_sync(0xffffffffu, s);
    if ((tid&31)==0 && n>=n0){
      if (warp==0) g_mA[n]=m; else g_mB[n]=m;
    }
  }
}

// ---------------- K4: spike-conv, FULLY PARALLEL (thread per row) ----------------
__global__ void __launch_bounds__(256) k_conv(const float* __restrict__ conv_w,  // (20,20,3)
                                              const float* __restrict__ conv_b){
  __shared__ float sw[60*20];   // [r*20+o]
  __shared__ float sb[20];
  int tid = threadIdx.x;
  for (int i=tid;i<1200;i+=256){ int o=i/60, r=i%60; sw[r*20+o]=conv_w[i]; }
  if (tid<20) sb[tid]=conv_b[tid];
  __syncthreads();
  int n = blockIdx.x*256+tid;
  unsigned ma=g_mA[n], mb=g_mB[n];
  float acc[20];
  #pragma unroll
  for (int o=0;o<20;o++) acc[o]=sb[o];
  #pragma unroll 4
  for (int r=0;r<32;r++){
    float pv = (float)((ma>>r)&1u);
    #pragma unroll
    for (int o=0;o<20;o++) acc[o]=fmaf(pv, sw[r*20+o], acc[o]);
  }
  #pragma unroll 4
  for (int r=0;r<28;r++){
    float pv = (float)((mb>>r)&1u);
    #pragma unroll
    for (int o=0;o<20;o++) acc[o]=fmaf(pv, sw[(32+r)*20+o], acc[o]);
  }
  float4* outp=(float4*)(g_c+(size_t)n*20);
  #pragma unroll
  for (int q=0;q<5;q++) outp[q]=make_float4(acc[4*q],acc[4*q+1],acc[4*q+2],acc[4*q+3]);
}

// ---------------- K5: LIF4 serial scan, minimal per-step work ----------------
__global__ void __launch_bounds__(32) k_lif4(){
  int lane = threadIdx.x;
  int n0 = blockIdx.x*HCH, n1 = n0+HCH;
  int s0 = n0 - HWARM; if (s0<0) s0=0;
  float v = 0.f;
  float cvn = (lane<20) ? g_c[(size_t)s0*20+lane] : -1.f;
  for (int n=s0; n<n1; ++n){
    float cv = cvn;
    if (n+1<n1 && lane<20) cvn = g_c[(size_t)(n+1)*20+lane];
    v = v + (cv - v)/TAU4f;
    bool s = (lane<20) && ((v - TH4) >= 0.f);
    if (s) v = 0.f;
    unsigned m = __ballot_sync(0xffffffffu, s);
    if (lane==0 && n>=n0) g_m4[n]=m;
  }
}

// ---------------- K6: fc(spikes4) + skip(in) + biases, FULLY PARALLEL ----------------
template<int OD>
__global__ void __launch_bounds__(256) k_post(const float* __restrict__ in,
                                              const float* __restrict__ skw,  // (OD,20,1)
                                              const float* __restrict__ skb,
                                              const float* __restrict__ fcw,  // (OD,20)
                                              const float* __restrict__ fcb,
                                              float* __restrict__ outp){
  __shared__ float ssk[20*OD];   // [f*OD+o]
  __shared__ float sfc[20*OD];   // [q*OD+o]
  __shared__ float sbb[OD];
  int tid=threadIdx.x;
  for (int i=tid;i<20*OD;i+=256){ int o=i/20, f=i%20; ssk[f*OD+o]=skw[i]; sfc[f*OD+o]=fcw[i]; }
  if (tid<OD) sbb[tid]=fcb[tid]+skb[tid];
  __syncthreads();
  int n = blockIdx.x*256+tid;
  float r[20];
  const float4* rp=(const float4*)(in+(size_t)n*20);
  #pragma unroll
  for (int q=0;q<5;q++){ float4 v=rp[q]; r[4*q]=v.x; r[4*q+1]=v.y; r[4*q+2]=v.z; r[4*q+3]=v.w; }
  unsigned m4 = g_m4[n];
  float acc[OD];
  #pragma unroll
  for (int o=0;o<OD;o++) acc[o]=sbb[o];
  #pragma unroll 4
  for (int f=0;f<20;f++){
    float xv=r[f];
    #pragma unroll
    for (int o=0;o<OD;o++) acc[o]=fmaf(xv, ssk[f*OD+o], acc[o]);
  }
  #pragma unroll 4
  for (int q=0;q<20;q++){
    float pv=(float)((m4>>q)&1u);
    #pragma unroll
    for (int o=0;o<OD;o++) acc[o]=fmaf(pv, sfc[q*OD+o], acc[o]);
  }
  #pragma unroll
  for (int o=0;o<OD;o++) outp[(size_t)n*OD+o]=acc[o];
}

// ---------------- K7: final LIF over batch + differential pairs ----------------
__global__ void __launch_bounds__(200) k_flif(){
  int tid = threadIdx.x;
  int d = tid % 10, j = tid / 10;
  int b0 = blockIdx.x*BCH, b1e = b0+BCH;
  int s0 = b0 - BWARM; if (s0<0) s0=0;
  float v[5] = {0.f,0.f,0.f,0.f,0.f};
  for (int b=s0; b<b1e; ++b){
    float sp[5];
    #pragma unroll
    for (int r=0;r<5;r++){
      float xv = g_o2[((size_t)b*SEQT + 5*j + r)*10 + d];
      v[r] = v[r] + (xv - v[r])/TAU4f;
      bool s = (v[r] - TH4) >= 0.f;
      if (s) v[r] = 0.f;
      sp[r] = s ? 1.f : 0.f;
    }
    if (b >= b0){
      float dp = (sp[3] + sp[4] - sp[0] - sp[1]) * 0.5f;
      g_dp[(size_t)b*200 + d*20 + j] = dp;
    }
  }
}

// ---------------- K8: fused = dp*avg, global moments ----------------
__global__ void __launch_bounds__(256) k_fused(){
  __shared__ float sdp[200];
  __shared__ float savg[20];
  __shared__ float rs[256];
  __shared__ float rq[256];
  int b = blockIdx.x, tid = threadIdx.x;
  if (tid<200) sdp[tid] = g_dp[(size_t)b*200 + tid];
  __syncthreads();
  if (tid<20){
    float a=0.f;
    #pragma unroll
    for (int d=0;d<10;d++) a += sdp[d*20+tid];
    savg[tid] = a*0.1f;
  }
  __syncthreads();
  float fu = 0.f;
  if (tid<200){
    fu = sdp[tid]*savg[tid%20];
    g_fused[(size_t)b*200 + tid] = fu;
  }
  rs[tid]=fu; rq[tid]=fu*fu;
  __syncthreads();
  for (int s=128; s>0; s>>=1){
    if (tid<s){ rs[tid]+=rs[tid+s]; rq[tid]+=rq[tid+s]; }
    __syncthreads();
  }
  if (tid==0){
    atomicAdd(&g_red[0], (double)rs[0]);
    atomicAdd(&g_red[1], (double)rq[0]);
  }
}

// ---------------- K9: BN + logits + log_softmax ----------------
__global__ void __launch_bounds__(32) k_out(const float* __restrict__ gamma,
                                            const float* __restrict__ beta,
                                            const float* __restrict__ clsw,
                                            const float* __restrict__ clsb,
                                            float* __restrict__ out){
  int b = blockIdx.x, lane = threadIdx.x;
  double inv = 1.0/(double)(BATCH*200);
  double mean = g_red[0]*inv;
  double var  = g_red[1]*inv - mean*mean;
  float fm = (float)mean;
  float rstd = (float)(1.0/sqrt(var + 1e-5));
  float gm = __ldg(&gamma[0]), bt = __ldg(&beta[0]);
  float p0=0.f, p1=0.f, p2=0.f;
  for (int j=lane; j<200; j+=32){
    float bnv = fmaf((g_fused[(size_t)b*200+j]-fm)*rstd, gm, bt);
    p0 = fmaf(bnv, __ldg(&clsw[j]),     p0);
    p1 = fmaf(bnv, __ldg(&clsw[200+j]), p1);
    p2 = fmaf(bnv, __ldg(&clsw[400+j]), p2);
  }
  #pragma unroll
  for (int s=16;s>0;s>>=1){
    p0 += __shfl_down_sync(0xffffffffu, p0, s);
    p1 += __shfl_down_sync(0xffffffffu, p1, s);
    p2 += __shfl_down_sync(0xffffffffu, p2, s);
  }
  if (lane==0){
    float l0 = p0 + __ldg(&clsb[0]);
    float l1 = p1 + __ldg(&clsb[1]);
    float l2 = p2 + __ldg(&clsb[2]);
    float m = fmaxf(l0, fmaxf(l1,l2));
    float lse = m + logf(expf(l0-m)+expf(l1-m)+expf(l2-m));
    out[b*3+0] = l0 - lse;
    out[b*3+1] = l1 - lse;
    out[b*3+2] = l2 - lse;
  }
}

// ---------------- launch ----------------
extern "C" void kernel_launch(void* const* d_in, const int* in_sizes, int n_in,
                              void* d_out, int out_size){
  (void)in_sizes; (void)n_in; (void)out_size;
  const float* x        = (const float*)d_in[0];
  const float* wih      = (const float*)d_in[1];
  const float* whh      = (const float*)d_in[2];
  const float* bih      = (const float*)d_in[3];
  const float* bhh      = (const float*)d_in[4];
  const float* sc_w     = (const float*)d_in[5];
  const float* sc_b     = (const float*)d_in[6];
  const float* c1w      = (const float*)d_in[7];
  const float* c1b      = (const float*)d_in[8];
  const float* f1w      = (const float*)d_in[9];
  const float* f1b      = (const float*)d_in[10];
  const float* s1w      = (const float*)d_in[11];
  const float* s1b      = (const float*)d_in[12];
  const float* c2w      = (const float*)d_in[13];
  const float* c2b      = (const float*)d_in[14];
  const float* f2w      = (const float*)d_in[15];
  const float* f2b      = (const float*)d_in[16];
  const float* s2w      = (const float*)d_in[17];
  const float* s2b      = (const float*)d_in[18];
  const float* gamma    = (const float*)d_in[19];
  const float* beta     = (const float*)d_in[20];
  const float* clsw     = (const float*)d_in[21];
  const float* clsb     = (const float*)d_in[22];
  float* out = (float*)d_out;

  float *p_cv, *p_o1, *p_o2;
  cudaGetSymbolAddress((void**)&p_cv,  g_cv);
  cudaGetSymbolAddress((void**)&p_o1,  g_o1);
  cudaGetSymbolAddress((void**)&p_o2,  g_o2);

  k_xgates<<<BATCH,256>>>(x, wih, bih, bhh);
  k_lstm<<<NLCH,32>>>(whh, sc_w, sc_b);

  k_mask<<<NHCH,64>>>(p_cv);
  k_conv<<<NTOT/256,256>>>(c1w, c1b);
  k_lif4<<<NHCH,32>>>();
  k_post<20><<<NTOT/256,256>>>(p_cv, s1w, s1b, f1w, f1b, p_o1);

  k_mask<<<NHCH,64>>>(p_o1);
  k_conv<<<NTOT/256,256>>>(c2w, c2b);
  k_lif4<<<NHCH,32>>>();
  k_post<10><<<NTOT/256,256>>>(p_o1, s2w, s2b, f2w, f2b, p_o2);

  k_flif<<<NBCH,200>>>();
  k_fused<<<BATCH,256>>>();
  k_out<<<BATCH,32>>>(gamma, beta, clsw, clsb, out);
}